// round 7
// baseline (speedup 1.0000x reference)
#include <cuda_runtime.h>
#include <math.h>
#include <stdint.h>

// Problem constants
#define BSZ 2
#define TLEN 2048
#define CDIM 1024
#define HN 16
#define DH 64
#define MROWS (BSZ * TLEN)   // 4096

// Scratch (allocation-free rule: __device__ globals)
__device__ float g_qkv[(size_t)MROWS * 3 * CDIM];   // tf32 values
__device__ float g_y[(size_t)MROWS * CDIM];         // tf32 values
__device__ float g_xc[(size_t)MROWS * CDIM];        // tf32(x)
__device__ float g_wt[(size_t)4 * CDIM * CDIM];     // tf32(W_attn^T), tf32(W_proj^T)

// ---------------------------------------------------------------------------
// helpers
// ---------------------------------------------------------------------------
__device__ __forceinline__ float to_tf32(float x) {
    uint32_t u;
    asm("cvt.rna.tf32.f32 %0, %1;" : "=r"(u) : "f"(x));
    return __uint_as_float(u);
}

__device__ __forceinline__ void mma_tf32(float* d, const uint32_t* a, const uint32_t* b) {
    asm volatile(
        "mma.sync.aligned.m16n8k8.row.col.f32.tf32.tf32.f32 "
        "{%0,%1,%2,%3}, {%4,%5,%6,%7}, {%8,%9}, {%0,%1,%2,%3};"
        : "+f"(d[0]), "+f"(d[1]), "+f"(d[2]), "+f"(d[3])
        : "r"(a[0]), "r"(a[1]), "r"(a[2]), "r"(a[3]), "r"(b[0]), "r"(b[1]));
}

__device__ __forceinline__ uint32_t smem_u32(const void* p) {
    uint32_t a;
    asm("{ .reg .u64 t; cvta.to.shared.u64 t, %1; cvt.u32.u64 %0, t; }"
        : "=r"(a) : "l"(p));
    return a;
}

__device__ __forceinline__ void ldsm_x4(uint32_t* r, uint32_t addr) {
    asm volatile("ldmatrix.sync.aligned.m8n8.x4.shared.b16 {%0,%1,%2,%3}, [%4];"
                 : "=r"(r[0]), "=r"(r[1]), "=r"(r[2]), "=r"(r[3]) : "r"(addr));
}

// a-frag (16x8, [m][k] smem): mats: (mlo,klo),(mhi,klo),(mlo,khi),(mhi,khi)
__device__ __forceinline__ uint32_t a_frag_off(int lane, int stride) {
    int mat = lane >> 3, rw = lane & 7;
    return (uint32_t)(((8 * (mat & 1) + rw) * stride + 4 * (mat >> 1)) * 4);
}
// b-frag pair (2 n-tiles, [n][k] smem): mats: (nt0,klo),(nt0,khi),(nt1,klo),(nt1,khi)
__device__ __forceinline__ uint32_t b_frag_off(int lane, int stride) {
    int mat = lane >> 3, rw = lane & 7;
    return (uint32_t)(((8 * (mat >> 1) + rw) * stride + 4 * (mat & 1)) * 4);
}

#define CP16(s, g) \
    asm volatile("cp.async.cg.shared.global [%0], [%1], 16;" :: "r"(s), "l"(g) : "memory")
#define CP_COMMIT() asm volatile("cp.async.commit_group;" ::: "memory")
#define CP_WAIT(n)  asm volatile("cp.async.wait_group %0;" :: "n"(n) : "memory")

// ---------------------------------------------------------------------------
// x -> tf32 conversion
// ---------------------------------------------------------------------------
__global__ __launch_bounds__(256) void cvt_kernel(const float* __restrict__ x)
{
    size_t i = ((size_t)blockIdx.x * 256 + threadIdx.x) * 4;
    float4 v = *(const float4*)(x + i);
    *(float4*)(g_xc + i) = make_float4(to_tf32(v.x), to_tf32(v.y),
                                       to_tf32(v.z), to_tf32(v.w));
}

// ---------------------------------------------------------------------------
// Weight transpose + tf32: src[K][N] -> g_wt(+off)[N][K]
// ---------------------------------------------------------------------------
__global__ __launch_bounds__(256) void transpose_kernel(
    const float* __restrict__ src, int K, int N, int sel)
{
    __shared__ float t[32][33];
    float* dst = g_wt + (sel ? (size_t)3 * CDIM * CDIM : 0);
    const int nb = blockIdx.x * 32, kb = blockIdx.y * 32;
    const int x = threadIdx.x, y = threadIdx.y;
#pragma unroll
    for (int j = 0; j < 32; j += 8)
        t[y + j][x] = src[(size_t)(kb + y + j) * N + nb + x];
    __syncthreads();
#pragma unroll
    for (int j = 0; j < 32; j += 8)
        dst[(size_t)(nb + y + j) * K + kb + x] = to_tf32(t[x][y + j]);
}

// ---------------------------------------------------------------------------
// tf32 GEMM: 128x128 tile, 128 threads = 4 warps (2m x 2n), warp tile 64x64.
// 3-stage cp.async ring; ldmatrix fragment feed; 32 HMMA per kk-step per warp.
// ---------------------------------------------------------------------------
#define SA 36
#define TBYTES (128 * SA * 4)
#define STAGEB (2 * TBYTES)
#define GSTAGES 3
#define GSMEM (GSTAGES * STAGEB)

__global__ __launch_bounds__(128) void gemm_ls_kernel(
    const float* __restrict__ bias, float* __restrict__ C_param,
    int M, int N, int K, int mode)
{
    extern __shared__ float smg[];
    const float* A  = mode ? g_y : g_xc;
    const float* Bt = g_wt + (mode ? (size_t)3 * CDIM * CDIM : 0);
    float*       C  = mode ? C_param : g_qkv;

    const int tid = threadIdx.x, lane = tid & 31, wid = tid >> 5;
    const int wm = wid >> 1, wn = wid & 1;
    const int g = lane >> 2, q = lane & 3;
    const int m0 = blockIdx.y * 128, n0 = blockIdx.x * 128;
    const uint32_t sb = smem_u32(smg);

    const uint32_t a_off = a_frag_off(lane, SA);
    const uint32_t b_off = b_frag_off(lane, SA);

    float acc[4][8][4];
#pragma unroll
    for (int mt = 0; mt < 4; mt++)
#pragma unroll
        for (int nt = 0; nt < 8; nt++)
#pragma unroll
            for (int e = 0; e < 4; e++) acc[mt][nt][e] = 0.f;

    const int nc = K / 32;

#pragma unroll
    for (int s = 0; s < 2; s++) {
        const int k0 = s * 32;
        const uint32_t st = sb + (uint32_t)(s * STAGEB);
#pragma unroll
        for (int i = 0; i < 8; i++) {
            const int f = tid + 128 * i;
            const int row = f >> 3, c4 = f & 7;
            const uint32_t so = st + (uint32_t)((row * SA + c4 * 4) * 4);
            CP16(so, A + (size_t)(m0 + row) * K + k0 + c4 * 4);
            CP16(so + TBYTES, Bt + (size_t)(n0 + row) * K + k0 + c4 * 4);
        }
        CP_COMMIT();
    }

    for (int c = 0; c < nc; c++) {
        CP_WAIT(1);
        __syncthreads();

        const uint32_t ab = sb + (uint32_t)((c % 3) * STAGEB);
        const uint32_t bbse = ab + TBYTES;
#pragma unroll
        for (int kk = 0; kk < 32; kk += 8) {
            uint32_t af[4][4], bf[4][4];
#pragma unroll
            for (int mt = 0; mt < 4; mt++)
                ldsm_x4(af[mt], ab + (uint32_t)(((wm * 64 + mt * 16) * SA + kk) * 4) + a_off);
#pragma unroll
            for (int pr = 0; pr < 4; pr++)
                ldsm_x4(bf[pr], bbse + (uint32_t)(((wn * 64 + pr * 16) * SA + kk) * 4) + b_off);
#pragma unroll
            for (int mt = 0; mt < 4; mt++)
#pragma unroll
                for (int nt = 0; nt < 8; nt++)
                    mma_tf32(acc[mt][nt], af[mt], bf[nt >> 1] + (nt & 1) * 2);
        }
        __syncthreads();

        if (c + 2 < nc) {
            const int k0 = (c + 2) * 32;
            const uint32_t st = sb + (uint32_t)(((c + 2) % 3) * STAGEB);
#pragma unroll
            for (int i = 0; i < 8; i++) {
                const int f = tid + 128 * i;
                const int row = f >> 3, c4 = f & 7;
                const uint32_t so = st + (uint32_t)((row * SA + c4 * 4) * 4);
                CP16(so, A + (size_t)(m0 + row) * K + k0 + c4 * 4);
                CP16(so + TBYTES, Bt + (size_t)(n0 + row) * K + k0 + c4 * 4);
            }
            CP_COMMIT();
        }
    }

#pragma unroll
    for (int mt = 0; mt < 4; mt++) {
        int r0 = m0 + wm * 64 + mt * 16 + g;
#pragma unroll
        for (int nt = 0; nt < 8; nt++) {
            int cc = n0 + wn * 64 + nt * 8 + 2 * q;
            float b0 = bias[cc], b1 = bias[cc + 1];
            float v00 = acc[mt][nt][0] + b0, v01 = acc[mt][nt][1] + b1;
            float v10 = acc[mt][nt][2] + b0, v11 = acc[mt][nt][3] + b1;
            if (mode == 0) {
                v00 = to_tf32(v00); v01 = to_tf32(v01);
                v10 = to_tf32(v10); v11 = to_tf32(v11);
            }
            *(float2*)(C + (size_t)r0 * N + cc)       = make_float2(v00, v01);
            *(float2*)(C + (size_t)(r0 + 8) * N + cc) = make_float2(v10, v11);
        }
    }
}

// ---------------------------------------------------------------------------
// Flash attention, tf32 mma + ldmatrix, DOUBLE-BUFFERED K/V stream.
// One block per (b,h,64-query tile); 128 threads = 4 warps (16 rows each).
// Smem: K0,V0,K1,V1 (2-stage cp.async ring), Vt. P aliases current K buffer
// (dead after S-mma; guarded by a barrier). Q staged through Vt, then frags
// hoisted to registers. 87,040 B -> 2 CTAs/SM.
// ---------------------------------------------------------------------------
#define SKA 68
#define TILE_F (64 * SKA)
#define TILE_B (TILE_F * 4)          // 17408
#define ASMEM (5 * TILE_B)           // 87040

__global__ __launch_bounds__(128, 2) void attn_db_kernel()
{
    extern __shared__ float sm[];
    float* Vt = sm + 4 * TILE_F;

    const int qt = (gridDim.x - 1) - blockIdx.x;   // heavy-first
    const int h = blockIdx.y, b = blockIdx.z;
    const int tid = threadIdx.x, lane = tid & 31, w = tid >> 5;
    const int g = lane >> 2, q = lane & 3;
    const int q0 = qt * 64;

    const uint32_t sb = smem_u32(sm);
    const uint32_t sVt = sb + 4 * TILE_B;

    const size_t rs = 3 * CDIM;
    const float* qb = g_qkv + (size_t)b * TLEN * rs + h * DH;
    const float* kb = qb + CDIM;
    const float* vb = qb + 2 * CDIM;

    const int lrow = tid >> 4;             // 0..7
    const int lcol = (tid & 15) * 4;       // 0..60
    const uint32_t aoff = a_frag_off(lane, SKA);
    const uint32_t boff = b_frag_off(lane, SKA);

    // ---- load Q (into Vt region) + prefetch K/V tile 0 (stage 0) ----
#pragma unroll
    for (int p = 0; p < 8; p++) {
        CP16(sVt + (uint32_t)(((lrow + 8 * p) * SKA + lcol) * 4),
             qb + (size_t)(q0 + lrow + 8 * p) * rs + lcol);
        uint32_t dk = sb + (uint32_t)(((lrow + 8 * p) * SKA + lcol) * 4);
        CP16(dk, kb + (size_t)(lrow + 8 * p) * rs + lcol);
        CP16(dk + TILE_B, vb + (size_t)(lrow + 8 * p) * rs + lcol);
    }
    CP_COMMIT(); CP_WAIT(0);
    __syncthreads();

    // hoist Q fragments (scaled by 1/sqrt(64), exact)
    uint32_t qf[8][4];
#pragma unroll
    for (int kd = 0; kd < 8; kd++) {
        ldsm_x4(qf[kd], sVt + (uint32_t)(((w * 16) * SKA + kd * 8) * 4) + aoff);
#pragma unroll
        for (int e = 0; e < 4; e++)
            qf[kd][e] = __float_as_uint(__uint_as_float(qf[kd][e]) * 0.125f);
    }

    float so[8][4];
    float mrow[2] = {-1e30f, -1e30f}, lsum[2] = {0.f, 0.f};
#pragma unroll
    for (int nt = 0; nt < 8; nt++)
#pragma unroll
        for (int e = 0; e < 4; e++) so[nt][e] = 0.f;

    for (int kt = 0; kt <= qt; kt++) {
        const uint32_t stK = sb + (uint32_t)((kt & 1) * 2 * TILE_B);
        float* Vcur = sm + (kt & 1) * 2 * TILE_F + TILE_F;
        float* Ps   = sm + (kt & 1) * 2 * TILE_F;   // aliases K-cur

        __syncthreads();   // prev iter's PV (P + Vt reads) fully complete
        if (kt < qt) {
            const uint32_t nK = sb + (uint32_t)(((kt + 1) & 1) * 2 * TILE_B);
            const int k0r = (kt + 1) * 64;
#pragma unroll
            for (int p = 0; p < 8; p++) {
                uint32_t dk = nK + (uint32_t)(((lrow + 8 * p) * SKA + lcol) * 4);
                CP16(dk, kb + (size_t)(k0r + lrow + 8 * p) * rs + lcol);
                CP16(dk + TILE_B, vb + (size_t)(k0r + lrow + 8 * p) * rs + lcol);
            }
            CP_COMMIT();
            CP_WAIT(1);    // current stage resident; next stays in flight
        } else {
            CP_WAIT(0);
        }
        __syncthreads();

        // ---- transpose V-cur -> Vt ----
        {
            const int td = tid & 63, tk = (tid >> 6) * 32;
#pragma unroll
            for (int i = 0; i < 8; i++) {
                const int k0 = tk + 4 * i;
                float4 v;
                v.x = Vcur[(k0 + 0) * SKA + td];
                v.y = Vcur[(k0 + 1) * SKA + td];
                v.z = Vcur[(k0 + 2) * SKA + td];
                v.w = Vcur[(k0 + 3) * SKA + td];
                *(float4*)&Vt[td * SKA + k0] = v;
            }
        }
        __syncthreads();

        // ---- S = Q K^T ----
        float sc[8][4];
#pragma unroll
        for (int nt = 0; nt < 8; nt++)
#pragma unroll
            for (int e = 0; e < 4; e++) sc[nt][e] = 0.f;

#pragma unroll
        for (int kd = 0; kd < 8; kd++) {
            uint32_t bf[4][4];
#pragma unroll
            for (int pr = 0; pr < 4; pr++)
                ldsm_x4(bf[pr], stK + (uint32_t)(((pr * 16) * SKA + kd * 8) * 4) + boff);
#pragma unroll
            for (int nt = 0; nt < 8; nt++)
                mma_tf32(sc[nt], qf[kd], bf[nt >> 1] + (nt & 1) * 2);
        }

        // ---- causal mask on diagonal tile ----
        if (kt == qt) {
            const int r0 = w * 16 + g, r1 = r0 + 8;
#pragma unroll
            for (int nt = 0; nt < 8; nt++) {
                const int c = nt * 8 + 2 * q;
                if (c     > r0) sc[nt][0] = -1e30f;
                if (c + 1 > r0) sc[nt][1] = -1e30f;
                if (c     > r1) sc[nt][2] = -1e30f;
                if (c + 1 > r1) sc[nt][3] = -1e30f;
            }
        }

        // ---- online softmax (2 rows per thread) ----
        float mx0 = -1e30f, mx1 = -1e30f;
#pragma unroll
        for (int nt = 0; nt < 8; nt++) {
            mx0 = fmaxf(mx0, fmaxf(sc[nt][0], sc[nt][1]));
            mx1 = fmaxf(mx1, fmaxf(sc[nt][2], sc[nt][3]));
        }
        mx0 = fmaxf(mx0, __shfl_xor_sync(0xffffffffu, mx0, 1));
        mx0 = fmaxf(mx0, __shfl_xor_sync(0xffffffffu, mx0, 2));
        mx1 = fmaxf(mx1, __shfl_xor_sync(0xffffffffu, mx1, 1));
        mx1 = fmaxf(mx1, __shfl_xor_sync(0xffffffffu, mx1, 2));

        const float mn0 = fmaxf(mrow[0], mx0);
        const float mn1 = fmaxf(mrow[1], mx1);
        const float al0 = __expf(mrow[0] - mn0);
        const float al1 = __expf(mrow[1] - mn1);
        mrow[0] = mn0; mrow[1] = mn1;

        float s0 = 0.f, s1 = 0.f;
#pragma unroll
        for (int nt = 0; nt < 8; nt++) {
            sc[nt][0] = __expf(sc[nt][0] - mn0); s0 += sc[nt][0];
            sc[nt][1] = __expf(sc[nt][1] - mn0); s0 += sc[nt][1];
            sc[nt][2] = __expf(sc[nt][2] - mn1); s1 += sc[nt][2];
            sc[nt][3] = __expf(sc[nt][3] - mn1); s1 += sc[nt][3];
        }
        s0 += __shfl_xor_sync(0xffffffffu, s0, 1);
        s0 += __shfl_xor_sync(0xffffffffu, s0, 2);
        s1 += __shfl_xor_sync(0xffffffffu, s1, 1);
        s1 += __shfl_xor_sync(0xffffffffu, s1, 2);
        lsum[0] = lsum[0] * al0 + s0;
        lsum[1] = lsum[1] * al1 + s1;

#pragma unroll
        for (int nt = 0; nt < 8; nt++) {
            so[nt][0] *= al0; so[nt][1] *= al0;
            so[nt][2] *= al1; so[nt][3] *= al1;
        }

        __syncthreads();   // all warps done reading K-cur before P overwrites it

        // ---- store P (tf32) over K-cur for a-frag reload ----
        {
            const int r0 = w * 16 + g;
#pragma unroll
            for (int nt = 0; nt < 8; nt++) {
                const int c = nt * 8 + 2 * q;
                *(float2*)&Ps[r0 * SKA + c] =
                    make_float2(to_tf32(sc[nt][0]), to_tf32(sc[nt][1]));
                *(float2*)&Ps[(r0 + 8) * SKA + c] =
                    make_float2(to_tf32(sc[nt][2]), to_tf32(sc[nt][3]));
            }
        }
        __syncwarp();   // P rows owned/read by this warp only

        // ---- O += P V ----
#pragma unroll
        for (int kd = 0; kd < 8; kd++) {
            uint32_t pf[4], bf[4][4];
            ldsm_x4(pf, stK + (uint32_t)(((w * 16) * SKA + kd * 8) * 4) + aoff);
#pragma unroll
            for (int pr = 0; pr < 4; pr++)
                ldsm_x4(bf[pr], sVt + (uint32_t)(((pr * 16) * SKA + kd * 8) * 4) + boff);
#pragma unroll
            for (int nt = 0; nt < 8; nt++)
                mma_tf32(so[nt], pf, bf[nt >> 1] + (nt & 1) * 2);
        }
    }

    // ---- normalize + store y (tf32 for GEMM2 consumption) ----
    {
        const float inv0 = 1.f / lsum[0];
        const float inv1 = 1.f / lsum[1];
        const int r0 = q0 + w * 16 + g;
        float* yb = g_y + (size_t)b * TLEN * CDIM + h * DH;
#pragma unroll
        for (int nt = 0; nt < 8; nt++) {
            const int c = nt * 8 + 2 * q;
            *(float2*)(yb + (size_t)r0 * CDIM + c) =
                make_float2(to_tf32(so[nt][0] * inv0), to_tf32(so[nt][1] * inv0));
            *(float2*)(yb + (size_t)(r0 + 8) * CDIM + c) =
                make_float2(to_tf32(so[nt][2] * inv1), to_tf32(so[nt][3] * inv1));
        }
    }
}

// ---------------------------------------------------------------------------
extern "C" void kernel_launch(void* const* d_in, const int* in_sizes, int n_in,
                              void* d_out, int out_size)
{
    const float* x      = (const float*)d_in[0];
    const float* W_attn = (const float*)d_in[1];
    const float* b_attn = (const float*)d_in[2];
    const float* W_proj = (const float*)d_in[3];
    const float* b_proj = (const float*)d_in[4];
    float* out = (float*)d_out;

    cudaFuncSetAttribute(gemm_ls_kernel, cudaFuncAttributeMaxDynamicSharedMemorySize, GSMEM);
    cudaFuncSetAttribute(attn_db_kernel, cudaFuncAttributeMaxDynamicSharedMemorySize, ASMEM);

    // 0) pre-convert x; transpose+convert weights
    cvt_kernel<<<(MROWS * CDIM) / (256 * 4), 256>>>(x);
    {
        dim3 tb(32, 8);
        transpose_kernel<<<dim3((3 * CDIM) / 32, CDIM / 32), tb>>>(W_attn, CDIM, 3 * CDIM, 0);
        transpose_kernel<<<dim3(CDIM / 32, CDIM / 32), tb>>>(W_proj, CDIM, CDIM, 1);
    }
    // 1) qkv = x @ W_attn + b_attn (tf32-rounded)
    {
        dim3 grid((3 * CDIM) / 128, MROWS / 128);
        gemm_ls_kernel<<<grid, 128, GSMEM>>>(b_attn, nullptr, MROWS, 3 * CDIM, CDIM, 0);
    }
    // 2) flash attention -> g_y (tf32-rounded)
    {
        dim3 grid(TLEN / 64, HN, BSZ);
        attn_db_kernel<<<grid, 128, ASMEM>>>();
    }
    // 3) out = y @ W_proj + b_proj
    {
        dim3 grid(CDIM / 128, MROWS / 128);
        gemm_ls_kernel<<<grid, 128, GSMEM>>>(b_proj, out, MROWS, CDIM, CDIM, 1);
    }
}

// round 8
// speedup vs baseline: 1.0578x; 1.0578x over previous
#include <cuda_runtime.h>
#include <math.h>
#include <stdint.h>

// Problem constants
#define BSZ 2
#define TLEN 2048
#define CDIM 1024
#define HN 16
#define DH 64
#define MROWS (BSZ * TLEN)   // 4096

// Scratch (allocation-free rule: __device__ globals)
__device__ float g_qkv[(size_t)MROWS * 3 * CDIM];   // tf32 values
__device__ float g_y[(size_t)MROWS * CDIM];         // tf32 values
__device__ float g_xc[(size_t)MROWS * CDIM];        // tf32(x)
__device__ float g_wt[(size_t)4 * CDIM * CDIM];     // tf32(W_attn^T), tf32(W_proj^T)
__device__ float g_vt[(size_t)BSZ * HN * DH * TLEN]; // V transposed: [b,h,d,t]

// ---------------------------------------------------------------------------
// helpers
// ---------------------------------------------------------------------------
__device__ __forceinline__ float to_tf32(float x) {
    uint32_t u;
    asm("cvt.rna.tf32.f32 %0, %1;" : "=r"(u) : "f"(x));
    return __uint_as_float(u);
}

__device__ __forceinline__ void mma_tf32(float* d, const uint32_t* a, const uint32_t* b) {
    asm volatile(
        "mma.sync.aligned.m16n8k8.row.col.f32.tf32.tf32.f32 "
        "{%0,%1,%2,%3}, {%4,%5,%6,%7}, {%8,%9}, {%0,%1,%2,%3};"
        : "+f"(d[0]), "+f"(d[1]), "+f"(d[2]), "+f"(d[3])
        : "r"(a[0]), "r"(a[1]), "r"(a[2]), "r"(a[3]), "r"(b[0]), "r"(b[1]));
}

__device__ __forceinline__ uint32_t smem_u32(const void* p) {
    uint32_t a;
    asm("{ .reg .u64 t; cvta.to.shared.u64 t, %1; cvt.u32.u64 %0, t; }"
        : "=r"(a) : "l"(p));
    return a;
}

__device__ __forceinline__ void ldsm_x4(uint32_t* r, uint32_t addr) {
    asm volatile("ldmatrix.sync.aligned.m8n8.x4.shared.b16 {%0,%1,%2,%3}, [%4];"
                 : "=r"(r[0]), "=r"(r[1]), "=r"(r[2]), "=r"(r[3]) : "r"(addr));
}

// a-frag (16x8, [m][k] smem): mats: (mlo,klo),(mhi,klo),(mlo,khi),(mhi,khi)
__device__ __forceinline__ uint32_t a_frag_off(int lane, int stride) {
    int mat = lane >> 3, rw = lane & 7;
    return (uint32_t)(((8 * (mat & 1) + rw) * stride + 4 * (mat >> 1)) * 4);
}
// b-frag pair (2 n-tiles, [n][k] smem): mats: (nt0,klo),(nt0,khi),(nt1,klo),(nt1,khi)
__device__ __forceinline__ uint32_t b_frag_off(int lane, int stride) {
    int mat = lane >> 3, rw = lane & 7;
    return (uint32_t)(((8 * (mat >> 1) + rw) * stride + 4 * (mat & 1)) * 4);
}

#define CP16(s, g) \
    asm volatile("cp.async.cg.shared.global [%0], [%1], 16;" :: "r"(s), "l"(g) : "memory")
#define CP_COMMIT() asm volatile("cp.async.commit_group;" ::: "memory")
#define CP_WAIT(n)  asm volatile("cp.async.wait_group %0;" :: "n"(n) : "memory")

// ---------------------------------------------------------------------------
// x -> tf32 conversion
// ---------------------------------------------------------------------------
__global__ __launch_bounds__(256) void cvt_kernel(const float* __restrict__ x)
{
    size_t i = ((size_t)blockIdx.x * 256 + threadIdx.x) * 4;
    float4 v = *(const float4*)(x + i);
    *(float4*)(g_xc + i) = make_float4(to_tf32(v.x), to_tf32(v.y),
                                       to_tf32(v.z), to_tf32(v.w));
}

// ---------------------------------------------------------------------------
// Weight transpose + tf32: src[K][N] -> g_wt(+off)[N][K]
// ---------------------------------------------------------------------------
__global__ __launch_bounds__(256) void transpose_kernel(
    const float* __restrict__ src, int K, int N, int sel)
{
    __shared__ float t[32][33];
    float* dst = g_wt + (sel ? (size_t)3 * CDIM * CDIM : 0);
    const int nb = blockIdx.x * 32, kb = blockIdx.y * 32;
    const int x = threadIdx.x, y = threadIdx.y;
#pragma unroll
    for (int j = 0; j < 32; j += 8)
        t[y + j][x] = src[(size_t)(kb + y + j) * N + nb + x];
    __syncthreads();
#pragma unroll
    for (int j = 0; j < 32; j += 8)
        dst[(size_t)(nb + y + j) * K + kb + x] = to_tf32(t[x][y + j]);
}

// ---------------------------------------------------------------------------
// V transpose: g_qkv V slice [b,t,(h,d)] -> g_vt[b,h,d,t]
// grid: (TLEN/32, 2*HN, BSZ), block (32,8)
// ---------------------------------------------------------------------------
__global__ __launch_bounds__(256) void vtrans_kernel()
{
    __shared__ float t[32][33];
    const int b = blockIdx.z;
    const int h = blockIdx.y >> 1;
    const int d0 = (blockIdx.y & 1) * 32;
    const int t0 = blockIdx.x * 32;
    const int x = threadIdx.x, y = threadIdx.y;

    const float* src = g_qkv + (size_t)b * TLEN * 3 * CDIM + 2 * CDIM + h * DH;
#pragma unroll
    for (int j = 0; j < 32; j += 8)
        t[y + j][x] = src[(size_t)(t0 + y + j) * 3 * CDIM + d0 + x];
    __syncthreads();
    float* dst = g_vt + ((size_t)(b * HN + h) * DH + d0) * TLEN + t0;
#pragma unroll
    for (int j = 0; j < 32; j += 8)
        dst[(size_t)(y + j) * TLEN + x] = t[x][y + j];
}

// ---------------------------------------------------------------------------
// tf32 GEMM: 128x128 tile, 128 threads = 4 warps (2m x 2n), warp tile 64x64.
// 3-stage cp.async ring, ONE barrier per chunk, prefetch before compute.
// ---------------------------------------------------------------------------
#define SA 36
#define TBYTES (128 * SA * 4)
#define STAGEB (2 * TBYTES)
#define GSTAGES 3
#define GSMEM (GSTAGES * STAGEB)

__global__ __launch_bounds__(128) void gemm_ls_kernel(
    const float* __restrict__ bias, float* __restrict__ C_param,
    int M, int N, int K, int mode)
{
    extern __shared__ float smg[];
    const float* A  = mode ? g_y : g_xc;
    const float* Bt = g_wt + (mode ? (size_t)3 * CDIM * CDIM : 0);
    float*       C  = mode ? C_param : g_qkv;

    const int tid = threadIdx.x, lane = tid & 31, wid = tid >> 5;
    const int wm = wid >> 1, wn = wid & 1;
    const int g = lane >> 2, q = lane & 3;
    const int m0 = blockIdx.y * 128, n0 = blockIdx.x * 128;
    const uint32_t sb = smem_u32(smg);

    const uint32_t a_off = a_frag_off(lane, SA);
    const uint32_t b_off = b_frag_off(lane, SA);

    float acc[4][8][4];
#pragma unroll
    for (int mt = 0; mt < 4; mt++)
#pragma unroll
        for (int nt = 0; nt < 8; nt++)
#pragma unroll
            for (int e = 0; e < 4; e++) acc[mt][nt][e] = 0.f;

    const int nc = K / 32;

#pragma unroll
    for (int s = 0; s < 2; s++) {
        const int k0 = s * 32;
        const uint32_t st = sb + (uint32_t)(s * STAGEB);
#pragma unroll
        for (int i = 0; i < 8; i++) {
            const int f = tid + 128 * i;
            const int row = f >> 3, c4 = f & 7;
            const uint32_t so = st + (uint32_t)((row * SA + c4 * 4) * 4);
            CP16(so, A + (size_t)(m0 + row) * K + k0 + c4 * 4);
            CP16(so + TBYTES, Bt + (size_t)(n0 + row) * K + k0 + c4 * 4);
        }
        CP_COMMIT();
    }

    for (int c = 0; c < nc; c++) {
        if (c == nc - 1) { CP_WAIT(0); } else { CP_WAIT(1); }
        __syncthreads();   // stage c resident for all; stage (c-1)%3 consumed by all

        // prefetch stage c+2 (overwrites stage (c-1)%3 — safe after the barrier)
        if (c + 2 < nc) {
            const int k0 = (c + 2) * 32;
            const uint32_t st = sb + (uint32_t)(((c + 2) % 3) * STAGEB);
#pragma unroll
            for (int i = 0; i < 8; i++) {
                const int f = tid + 128 * i;
                const int row = f >> 3, c4 = f & 7;
                const uint32_t so = st + (uint32_t)((row * SA + c4 * 4) * 4);
                CP16(so, A + (size_t)(m0 + row) * K + k0 + c4 * 4);
                CP16(so + TBYTES, Bt + (size_t)(n0 + row) * K + k0 + c4 * 4);
            }
            CP_COMMIT();
        }

        const uint32_t ab = sb + (uint32_t)((c % 3) * STAGEB);
        const uint32_t bbse = ab + TBYTES;
#pragma unroll
        for (int kk = 0; kk < 32; kk += 8) {
            uint32_t af[4][4], bf[4][4];
#pragma unroll
            for (int mt = 0; mt < 4; mt++)
                ldsm_x4(af[mt], ab + (uint32_t)(((wm * 64 + mt * 16) * SA + kk) * 4) + a_off);
#pragma unroll
            for (int pr = 0; pr < 4; pr++)
                ldsm_x4(bf[pr], bbse + (uint32_t)(((wn * 64 + pr * 16) * SA + kk) * 4) + b_off);
#pragma unroll
            for (int mt = 0; mt < 4; mt++)
#pragma unroll
                for (int nt = 0; nt < 8; nt++)
                    mma_tf32(acc[mt][nt], af[mt], bf[nt >> 1] + (nt & 1) * 2);
        }
    }

#pragma unroll
    for (int mt = 0; mt < 4; mt++) {
        int r0 = m0 + wm * 64 + mt * 16 + g;
#pragma unroll
        for (int nt = 0; nt < 8; nt++) {
            int cc = n0 + wn * 64 + nt * 8 + 2 * q;
            float b0 = bias[cc], b1 = bias[cc + 1];
            float v00 = acc[mt][nt][0] + b0, v01 = acc[mt][nt][1] + b1;
            float v10 = acc[mt][nt][2] + b0, v11 = acc[mt][nt][3] + b1;
            if (mode == 0) {
                v00 = to_tf32(v00); v01 = to_tf32(v01);
                v10 = to_tf32(v10); v11 = to_tf32(v11);
            }
            *(float2*)(C + (size_t)r0 * N + cc)       = make_float2(v00, v01);
            *(float2*)(C + (size_t)(r0 + 8) * N + cc) = make_float2(v10, v11);
        }
    }
}

// ---------------------------------------------------------------------------
// Flash attention, tf32 mma + ldmatrix, PRE-TRANSPOSED V (no smem transpose).
// One block per (b,h,64-query tile); 128 threads = 4 warps (16 rows each).
// Smem: K [64xSKA] | Vt [64xSKA] | P/Qstage [64xSKA] = 52,224 B -> 3 CTAs/SM.
// 2 barriers per kt-iteration.
// ---------------------------------------------------------------------------
#define SKA 68
#define TILE_F (64 * SKA)
#define TILE_B (TILE_F * 4)          // 17408
#define ASMEM (3 * TILE_B)           // 52224

__global__ __launch_bounds__(128, 3) void attn_vt_kernel()
{
    extern __shared__ float sm[];

    const int qt = (gridDim.x - 1) - blockIdx.x;   // heavy-first
    const int h = blockIdx.y, b = blockIdx.z;
    const int tid = threadIdx.x, lane = tid & 31, w = tid >> 5;
    const int g = lane >> 2, q = lane & 3;
    const int q0 = qt * 64;

    const uint32_t sb = smem_u32(sm);
    const uint32_t sK = sb, sVt = sb + TILE_B, sP = sb + 2 * TILE_B;
    float* Ps = sm + 2 * TILE_F;

    const size_t rs = 3 * CDIM;
    const float* qb  = g_qkv + (size_t)b * TLEN * rs + h * DH;
    const float* kb  = qb + CDIM;
    const float* vtb = g_vt + (size_t)(b * HN + h) * DH * TLEN;

    const int lrow = tid >> 4;             // 0..7
    const int lcol = (tid & 15) * 4;       // 0..60
    const uint32_t aoff = a_frag_off(lane, SKA);
    const uint32_t boff = b_frag_off(lane, SKA);

    // ---- load Q into P buffer, hoist fragments (scaled 0.125, exact) ----
#pragma unroll
    for (int p = 0; p < 8; p++) {
        CP16(sP + (uint32_t)(((lrow + 8 * p) * SKA + lcol) * 4),
             qb + (size_t)(q0 + lrow + 8 * p) * rs + lcol);
    }
    CP_COMMIT(); CP_WAIT(0);
    __syncthreads();

    uint32_t qf[8][4];
#pragma unroll
    for (int kd = 0; kd < 8; kd++) {
        ldsm_x4(qf[kd], sP + (uint32_t)(((w * 16) * SKA + kd * 8) * 4) + aoff);
#pragma unroll
        for (int e = 0; e < 4; e++)
            qf[kd][e] = __float_as_uint(__uint_as_float(qf[kd][e]) * 0.125f);
    }

    float so[8][4];
    float mrow[2] = {-1e30f, -1e30f}, lsum[2] = {0.f, 0.f};
#pragma unroll
    for (int nt = 0; nt < 8; nt++)
#pragma unroll
        for (int e = 0; e < 4; e++) so[nt][e] = 0.f;

    for (int kt = 0; kt <= qt; kt++) {
        __syncthreads();   // prev iter's K/Vt/P reads fully complete (also Q hoist on kt=0)
        {
            const int k0r = kt * 64;
#pragma unroll
            for (int p = 0; p < 8; p++) {
                // K tile: rows = keys, cols = head dim
                CP16(sK + (uint32_t)(((lrow + 8 * p) * SKA + lcol) * 4),
                     kb + (size_t)(k0r + lrow + 8 * p) * rs + lcol);
                // V^T tile: rows = head dim, cols = keys
                CP16(sVt + (uint32_t)(((lrow + 8 * p) * SKA + lcol) * 4),
                     vtb + (size_t)(lrow + 8 * p) * TLEN + k0r + lcol);
            }
            CP_COMMIT(); CP_WAIT(0);
        }
        __syncthreads();

        // ---- S = Q K^T ----
        float sc[8][4];
#pragma unroll
        for (int nt = 0; nt < 8; nt++)
#pragma unroll
            for (int e = 0; e < 4; e++) sc[nt][e] = 0.f;

#pragma unroll
        for (int kd = 0; kd < 8; kd++) {
            uint32_t bf[4][4];
#pragma unroll
            for (int pr = 0; pr < 4; pr++)
                ldsm_x4(bf[pr], sK + (uint32_t)(((pr * 16) * SKA + kd * 8) * 4) + boff);
#pragma unroll
            for (int nt = 0; nt < 8; nt++)
                mma_tf32(sc[nt], qf[kd], bf[nt >> 1] + (nt & 1) * 2);
        }

        // ---- causal mask on diagonal tile ----
        if (kt == qt) {
            const int r0 = w * 16 + g, r1 = r0 + 8;
#pragma unroll
            for (int nt = 0; nt < 8; nt++) {
                const int c = nt * 8 + 2 * q;
                if (c     > r0) sc[nt][0] = -1e30f;
                if (c + 1 > r0) sc[nt][1] = -1e30f;
                if (c     > r1) sc[nt][2] = -1e30f;
                if (c + 1 > r1) sc[nt][3] = -1e30f;
            }
        }

        // ---- online softmax (2 rows per thread) ----
        float mx0 = -1e30f, mx1 = -1e30f;
#pragma unroll
        for (int nt = 0; nt < 8; nt++) {
            mx0 = fmaxf(mx0, fmaxf(sc[nt][0], sc[nt][1]));
            mx1 = fmaxf(mx1, fmaxf(sc[nt][2], sc[nt][3]));
        }
        mx0 = fmaxf(mx0, __shfl_xor_sync(0xffffffffu, mx0, 1));
        mx0 = fmaxf(mx0, __shfl_xor_sync(0xffffffffu, mx0, 2));
        mx1 = fmaxf(mx1, __shfl_xor_sync(0xffffffffu, mx1, 1));
        mx1 = fmaxf(mx1, __shfl_xor_sync(0xffffffffu, mx1, 2));

        const float mn0 = fmaxf(mrow[0], mx0);
        const float mn1 = fmaxf(mrow[1], mx1);
        const float al0 = __expf(mrow[0] - mn0);
        const float al1 = __expf(mrow[1] - mn1);
        mrow[0] = mn0; mrow[1] = mn1;

        float s0 = 0.f, s1 = 0.f;
#pragma unroll
        for (int nt = 0; nt < 8; nt++) {
            sc[nt][0] = __expf(sc[nt][0] - mn0); s0 += sc[nt][0];
            sc[nt][1] = __expf(sc[nt][1] - mn0); s0 += sc[nt][1];
            sc[nt][2] = __expf(sc[nt][2] - mn1); s1 += sc[nt][2];
            sc[nt][3] = __expf(sc[nt][3] - mn1); s1 += sc[nt][3];
        }
        s0 += __shfl_xor_sync(0xffffffffu, s0, 1);
        s0 += __shfl_xor_sync(0xffffffffu, s0, 2);
        s1 += __shfl_xor_sync(0xffffffffu, s1, 1);
        s1 += __shfl_xor_sync(0xffffffffu, s1, 2);
        lsum[0] = lsum[0] * al0 + s0;
        lsum[1] = lsum[1] * al1 + s1;

#pragma unroll
        for (int nt = 0; nt < 8; nt++) {
            so[nt][0] *= al0; so[nt][1] *= al0;
            so[nt][2] *= al1; so[nt][3] *= al1;
        }

        // ---- store P (tf32) into its own buffer (own warp rows only) ----
        {
            const int r0 = w * 16 + g;
#pragma unroll
            for (int nt = 0; nt < 8; nt++) {
                const int c = nt * 8 + 2 * q;
                *(float2*)&Ps[r0 * SKA + c] =
                    make_float2(to_tf32(sc[nt][0]), to_tf32(sc[nt][1]));
                *(float2*)&Ps[(r0 + 8) * SKA + c] =
                    make_float2(to_tf32(sc[nt][2]), to_tf32(sc[nt][3]));
            }
        }
        __syncwarp();   // P rows owned/read by this warp only

        // ---- O += P V  (b-frags straight from pre-transposed V) ----
#pragma unroll
        for (int kd = 0; kd < 8; kd++) {
            uint32_t pf[4], bf[4][4];
            ldsm_x4(pf, sP + (uint32_t)(((w * 16) * SKA + kd * 8) * 4) + aoff);
#pragma unroll
            for (int pr = 0; pr < 4; pr++)
                ldsm_x4(bf[pr], sVt + (uint32_t)(((pr * 16) * SKA + kd * 8) * 4) + boff);
#pragma unroll
            for (int nt = 0; nt < 8; nt++)
                mma_tf32(so[nt], pf, bf[nt >> 1] + (nt & 1) * 2);
        }
    }

    // ---- normalize + store y (tf32 for GEMM2 consumption) ----
    {
        const float inv0 = 1.f / lsum[0];
        const float inv1 = 1.f / lsum[1];
        const int r0 = q0 + w * 16 + g;
        float* yb = g_y + (size_t)b * TLEN * CDIM + h * DH;
#pragma unroll
        for (int nt = 0; nt < 8; nt++) {
            const int c = nt * 8 + 2 * q;
            *(float2*)(yb + (size_t)r0 * CDIM + c) =
                make_float2(to_tf32(so[nt][0] * inv0), to_tf32(so[nt][1] * inv0));
            *(float2*)(yb + (size_t)(r0 + 8) * CDIM + c) =
                make_float2(to_tf32(so[nt][2] * inv1), to_tf32(so[nt][3] * inv1));
        }
    }
}

// ---------------------------------------------------------------------------
extern "C" void kernel_launch(void* const* d_in, const int* in_sizes, int n_in,
                              void* d_out, int out_size)
{
    const float* x      = (const float*)d_in[0];
    const float* W_attn = (const float*)d_in[1];
    const float* b_attn = (const float*)d_in[2];
    const float* W_proj = (const float*)d_in[3];
    const float* b_proj = (const float*)d_in[4];
    float* out = (float*)d_out;

    cudaFuncSetAttribute(gemm_ls_kernel, cudaFuncAttributeMaxDynamicSharedMemorySize, GSMEM);
    cudaFuncSetAttribute(attn_vt_kernel, cudaFuncAttributeMaxDynamicSharedMemorySize, ASMEM);

    // 0) pre-convert x; transpose+convert weights
    cvt_kernel<<<(MROWS * CDIM) / (256 * 4), 256>>>(x);
    {
        dim3 tb(32, 8);
        transpose_kernel<<<dim3((3 * CDIM) / 32, CDIM / 32), tb>>>(W_attn, CDIM, 3 * CDIM, 0);
        transpose_kernel<<<dim3(CDIM / 32, CDIM / 32), tb>>>(W_proj, CDIM, CDIM, 1);
    }
    // 1) qkv = x @ W_attn + b_attn (tf32-rounded)
    {
        dim3 grid((3 * CDIM) / 128, MROWS / 128);
        gemm_ls_kernel<<<grid, 128, GSMEM>>>(b_attn, nullptr, MROWS, 3 * CDIM, CDIM, 0);
    }
    // 1b) transpose V slice: g_qkv -> g_vt[b,h,d,t]
    {
        dim3 tb(32, 8);
        vtrans_kernel<<<dim3(TLEN / 32, 2 * HN, BSZ), tb>>>();
    }
    // 2) flash attention -> g_y (tf32-rounded)
    {
        dim3 grid(TLEN / 64, HN, BSZ);
        attn_vt_kernel<<<grid, 128, ASMEM>>>();
    }
    // 3) out = y @ W_proj + b_proj
    {
        dim3 grid(CDIM / 128, MROWS / 128);
        gemm_ls_kernel<<<grid, 128, GSMEM>>>(b_proj, out, MROWS, CDIM, CDIM, 1);
    }
}

// round 9
// speedup vs baseline: 1.0882x; 1.0287x over previous
#include <cuda_runtime.h>
#include <math.h>
#include <stdint.h>

// Problem constants
#define BSZ 2
#define TLEN 2048
#define CDIM 1024
#define HN 16
#define DH 64
#define MROWS (BSZ * TLEN)   // 4096

// Scratch (allocation-free rule: __device__ globals)
__device__ float g_qkv[(size_t)MROWS * 3 * CDIM];   // tf32 values
__device__ float g_y[(size_t)MROWS * CDIM];         // tf32 values
__device__ float g_xc[(size_t)MROWS * CDIM];        // tf32(x)
__device__ float g_wt[(size_t)4 * CDIM * CDIM];     // tf32(W_attn^T), tf32(W_proj^T)
__device__ float g_vt[(size_t)BSZ * HN * DH * TLEN]; // V transposed: [b,h,d,t]

// ---------------------------------------------------------------------------
// helpers
// ---------------------------------------------------------------------------
__device__ __forceinline__ float to_tf32(float x) {
    uint32_t u;
    asm("cvt.rna.tf32.f32 %0, %1;" : "=r"(u) : "f"(x));
    return __uint_as_float(u);
}

__device__ __forceinline__ void mma_tf32(float* d, const uint32_t* a, const uint32_t* b) {
    asm volatile(
        "mma.sync.aligned.m16n8k8.row.col.f32.tf32.tf32.f32 "
        "{%0,%1,%2,%3}, {%4,%5,%6,%7}, {%8,%9}, {%0,%1,%2,%3};"
        : "+f"(d[0]), "+f"(d[1]), "+f"(d[2]), "+f"(d[3])
        : "r"(a[0]), "r"(a[1]), "r"(a[2]), "r"(a[3]), "r"(b[0]), "r"(b[1]));
}

__device__ __forceinline__ uint32_t smem_u32(const void* p) {
    uint32_t a;
    asm("{ .reg .u64 t; cvta.to.shared.u64 t, %1; cvt.u32.u64 %0, t; }"
        : "=r"(a) : "l"(p));
    return a;
}

__device__ __forceinline__ void ldsm_x4(uint32_t* r, uint32_t addr) {
    asm volatile("ldmatrix.sync.aligned.m8n8.x4.shared.b16 {%0,%1,%2,%3}, [%4];"
                 : "=r"(r[0]), "=r"(r[1]), "=r"(r[2]), "=r"(r[3]) : "r"(addr));
}

// a-frag (16x8, [m][k] smem): mats: (mlo,klo),(mhi,klo),(mlo,khi),(mhi,khi)
__device__ __forceinline__ uint32_t a_frag_off(int lane, int stride) {
    int mat = lane >> 3, rw = lane & 7;
    return (uint32_t)(((8 * (mat & 1) + rw) * stride + 4 * (mat >> 1)) * 4);
}
// b-frag pair (2 n-tiles, [n][k] smem): mats: (nt0,klo),(nt0,khi),(nt1,klo),(nt1,khi)
__device__ __forceinline__ uint32_t b_frag_off(int lane, int stride) {
    int mat = lane >> 3, rw = lane & 7;
    return (uint32_t)(((8 * (mat >> 1) + rw) * stride + 4 * (mat & 1)) * 4);
}

#define CP16(s, g) \
    asm volatile("cp.async.cg.shared.global [%0], [%1], 16;" :: "r"(s), "l"(g) : "memory")
#define CP_COMMIT() asm volatile("cp.async.commit_group;" ::: "memory")
#define CP_WAIT(n)  asm volatile("cp.async.wait_group %0;" :: "n"(n) : "memory")

// ---------------------------------------------------------------------------
// x -> tf32 conversion
// ---------------------------------------------------------------------------
__global__ __launch_bounds__(256) void cvt_kernel(const float* __restrict__ x)
{
    size_t i = ((size_t)blockIdx.x * 256 + threadIdx.x) * 4;
    float4 v = *(const float4*)(x + i);
    *(float4*)(g_xc + i) = make_float4(to_tf32(v.x), to_tf32(v.y),
                                       to_tf32(v.z), to_tf32(v.w));
}

// ---------------------------------------------------------------------------
// Weight transpose + tf32: src[K][N] -> g_wt(+off)[N][K]
// ---------------------------------------------------------------------------
__global__ __launch_bounds__(256) void transpose_kernel(
    const float* __restrict__ src, int K, int N, int sel)
{
    __shared__ float t[32][33];
    float* dst = g_wt + (sel ? (size_t)3 * CDIM * CDIM : 0);
    const int nb = blockIdx.x * 32, kb = blockIdx.y * 32;
    const int x = threadIdx.x, y = threadIdx.y;
#pragma unroll
    for (int j = 0; j < 32; j += 8)
        t[y + j][x] = src[(size_t)(kb + y + j) * N + nb + x];
    __syncthreads();
#pragma unroll
    for (int j = 0; j < 32; j += 8)
        dst[(size_t)(nb + y + j) * K + kb + x] = to_tf32(t[x][y + j]);
}

// ---------------------------------------------------------------------------
// V transpose: g_qkv V slice [b,t,(h,d)] -> g_vt[b,h,d,t]
// grid: (TLEN/32, 2*HN, BSZ), block (32,8)
// ---------------------------------------------------------------------------
__global__ __launch_bounds__(256) void vtrans_kernel()
{
    __shared__ float t[32][33];
    const int b = blockIdx.z;
    const int h = blockIdx.y >> 1;
    const int d0 = (blockIdx.y & 1) * 32;
    const int t0 = blockIdx.x * 32;
    const int x = threadIdx.x, y = threadIdx.y;

    const float* src = g_qkv + (size_t)b * TLEN * 3 * CDIM + 2 * CDIM + h * DH;
#pragma unroll
    for (int j = 0; j < 32; j += 8)
        t[y + j][x] = src[(size_t)(t0 + y + j) * 3 * CDIM + d0 + x];
    __syncthreads();
    float* dst = g_vt + ((size_t)(b * HN + h) * DH + d0) * TLEN + t0;
#pragma unroll
    for (int j = 0; j < 32; j += 8)
        dst[(size_t)(y + j) * TLEN + x] = t[x][y + j];
}

// ---------------------------------------------------------------------------
// tf32 GEMM: 128x128 tile, 128 threads = 4 warps (2m x 2n), warp tile 64x64.
// 2-stage cp.async ring (73.7 KB) -> 3 CTAs/SM; ldmatrix fragment feed.
// ---------------------------------------------------------------------------
#define SA 36
#define TBYTES (128 * SA * 4)
#define STAGEB (2 * TBYTES)
#define GSTAGES 2
#define GSMEM (GSTAGES * STAGEB)     // 73728

__global__ __launch_bounds__(128, 3) void gemm_ls_kernel(
    const float* __restrict__ bias, float* __restrict__ C_param,
    int M, int N, int K, int mode)
{
    extern __shared__ float smg[];
    const float* A  = mode ? g_y : g_xc;
    const float* Bt = g_wt + (mode ? (size_t)3 * CDIM * CDIM : 0);
    float*       C  = mode ? C_param : g_qkv;

    const int tid = threadIdx.x, lane = tid & 31, wid = tid >> 5;
    const int wm = wid >> 1, wn = wid & 1;
    const int g = lane >> 2, q = lane & 3;
    const int m0 = blockIdx.y * 128, n0 = blockIdx.x * 128;
    const uint32_t sb = smem_u32(smg);

    const uint32_t a_off = a_frag_off(lane, SA);
    const uint32_t b_off = b_frag_off(lane, SA);

    float acc[4][8][4];
#pragma unroll
    for (int mt = 0; mt < 4; mt++)
#pragma unroll
        for (int nt = 0; nt < 8; nt++)
#pragma unroll
            for (int e = 0; e < 4; e++) acc[mt][nt][e] = 0.f;

    const int nc = K / 32;

    // prefetch stages 0 and 1
#pragma unroll
    for (int s = 0; s < 2; s++) {
        const int k0 = s * 32;
        const uint32_t st = sb + (uint32_t)(s * STAGEB);
#pragma unroll
        for (int i = 0; i < 8; i++) {
            const int f = tid + 128 * i;
            const int row = f >> 3, c4 = f & 7;
            const uint32_t so = st + (uint32_t)((row * SA + c4 * 4) * 4);
            CP16(so, A + (size_t)(m0 + row) * K + k0 + c4 * 4);
            CP16(so + TBYTES, Bt + (size_t)(n0 + row) * K + k0 + c4 * 4);
        }
        CP_COMMIT();
    }

    for (int c = 0; c < nc; c++) {
        if (c == nc - 1) { CP_WAIT(0); } else { CP_WAIT(1); }
        __syncthreads();   // stage c visible to all warps

        const uint32_t ab = sb + (uint32_t)((c & 1) * STAGEB);
        const uint32_t bbse = ab + TBYTES;
#pragma unroll
        for (int kk = 0; kk < 32; kk += 8) {
            uint32_t af[4][4], bf[4][4];
#pragma unroll
            for (int mt = 0; mt < 4; mt++)
                ldsm_x4(af[mt], ab + (uint32_t)(((wm * 64 + mt * 16) * SA + kk) * 4) + a_off);
#pragma unroll
            for (int pr = 0; pr < 4; pr++)
                ldsm_x4(bf[pr], bbse + (uint32_t)(((wn * 64 + pr * 16) * SA + kk) * 4) + b_off);
#pragma unroll
            for (int mt = 0; mt < 4; mt++)
#pragma unroll
                for (int nt = 0; nt < 8; nt++)
                    mma_tf32(acc[mt][nt], af[mt], bf[nt >> 1] + (nt & 1) * 2);
        }
        __syncthreads();   // all warps done with stage c before it is refilled

        if (c + 2 < nc) {
            const int k0 = (c + 2) * 32;
            const uint32_t st = sb + (uint32_t)((c & 1) * STAGEB);  // (c+2)%2 == c%2
#pragma unroll
            for (int i = 0; i < 8; i++) {
                const int f = tid + 128 * i;
                const int row = f >> 3, c4 = f & 7;
                const uint32_t so = st + (uint32_t)((row * SA + c4 * 4) * 4);
                CP16(so, A + (size_t)(m0 + row) * K + k0 + c4 * 4);
                CP16(so + TBYTES, Bt + (size_t)(n0 + row) * K + k0 + c4 * 4);
            }
            CP_COMMIT();
        }
    }

#pragma unroll
    for (int mt = 0; mt < 4; mt++) {
        int r0 = m0 + wm * 64 + mt * 16 + g;
#pragma unroll
        for (int nt = 0; nt < 8; nt++) {
            int cc = n0 + wn * 64 + nt * 8 + 2 * q;
            float b0 = bias[cc], b1 = bias[cc + 1];
            float v00 = acc[mt][nt][0] + b0, v01 = acc[mt][nt][1] + b1;
            float v10 = acc[mt][nt][2] + b0, v11 = acc[mt][nt][3] + b1;
            if (mode == 0) {
                v00 = to_tf32(v00); v01 = to_tf32(v01);
                v10 = to_tf32(v10); v11 = to_tf32(v11);
            }
            *(float2*)(C + (size_t)r0 * N + cc)       = make_float2(v00, v01);
            *(float2*)(C + (size_t)(r0 + 8) * N + cc) = make_float2(v10, v11);
        }
    }
}

// ---------------------------------------------------------------------------
// Flash attention, tf32 mma + ldmatrix, PRE-TRANSPOSED V (unchanged from R8).
// Smem: K | Vt | P/Qstage = 52,224 B -> 3 CTAs/SM.
// ---------------------------------------------------------------------------
#define SKA 68
#define TILE_F (64 * SKA)
#define TILE_B (TILE_F * 4)          // 17408
#define ASMEM (3 * TILE_B)           // 52224

__global__ __launch_bounds__(128, 3) void attn_vt_kernel()
{
    extern __shared__ float sm[];

    const int qt = (gridDim.x - 1) - blockIdx.x;   // heavy-first
    const int h = blockIdx.y, b = blockIdx.z;
    const int tid = threadIdx.x, lane = tid & 31, w = tid >> 5;
    const int g = lane >> 2, q = lane & 3;
    const int q0 = qt * 64;

    const uint32_t sb = smem_u32(sm);
    const uint32_t sK = sb, sVt = sb + TILE_B, sP = sb + 2 * TILE_B;
    float* Ps = sm + 2 * TILE_F;

    const size_t rs = 3 * CDIM;
    const float* qb  = g_qkv + (size_t)b * TLEN * rs + h * DH;
    const float* kb  = qb + CDIM;
    const float* vtb = g_vt + (size_t)(b * HN + h) * DH * TLEN;

    const int lrow = tid >> 4;             // 0..7
    const int lcol = (tid & 15) * 4;       // 0..60
    const uint32_t aoff = a_frag_off(lane, SKA);
    const uint32_t boff = b_frag_off(lane, SKA);

    // ---- load Q into P buffer, hoist fragments (scaled 0.125, exact) ----
#pragma unroll
    for (int p = 0; p < 8; p++) {
        CP16(sP + (uint32_t)(((lrow + 8 * p) * SKA + lcol) * 4),
             qb + (size_t)(q0 + lrow + 8 * p) * rs + lcol);
    }
    CP_COMMIT(); CP_WAIT(0);
    __syncthreads();

    uint32_t qf[8][4];
#pragma unroll
    for (int kd = 0; kd < 8; kd++) {
        ldsm_x4(qf[kd], sP + (uint32_t)(((w * 16) * SKA + kd * 8) * 4) + aoff);
#pragma unroll
        for (int e = 0; e < 4; e++)
            qf[kd][e] = __float_as_uint(__uint_as_float(qf[kd][e]) * 0.125f);
    }

    float so[8][4];
    float mrow[2] = {-1e30f, -1e30f}, lsum[2] = {0.f, 0.f};
#pragma unroll
    for (int nt = 0; nt < 8; nt++)
#pragma unroll
        for (int e = 0; e < 4; e++) so[nt][e] = 0.f;

    for (int kt = 0; kt <= qt; kt++) {
        __syncthreads();   // prev iter's K/Vt/P reads fully complete (also Q hoist on kt=0)
        {
            const int k0r = kt * 64;
#pragma unroll
            for (int p = 0; p < 8; p++) {
                CP16(sK + (uint32_t)(((lrow + 8 * p) * SKA + lcol) * 4),
                     kb + (size_t)(k0r + lrow + 8 * p) * rs + lcol);
                CP16(sVt + (uint32_t)(((lrow + 8 * p) * SKA + lcol) * 4),
                     vtb + (size_t)(lrow + 8 * p) * TLEN + k0r + lcol);
            }
            CP_COMMIT(); CP_WAIT(0);
        }
        __syncthreads();

        // ---- S = Q K^T ----
        float sc[8][4];
#pragma unroll
        for (int nt = 0; nt < 8; nt++)
#pragma unroll
            for (int e = 0; e < 4; e++) sc[nt][e] = 0.f;

#pragma unroll
        for (int kd = 0; kd < 8; kd++) {
            uint32_t bf[4][4];
#pragma unroll
            for (int pr = 0; pr < 4; pr++)
                ldsm_x4(bf[pr], sK + (uint32_t)(((pr * 16) * SKA + kd * 8) * 4) + boff);
#pragma unroll
            for (int nt = 0; nt < 8; nt++)
                mma_tf32(sc[nt], qf[kd], bf[nt >> 1] + (nt & 1) * 2);
        }

        // ---- causal mask on diagonal tile ----
        if (kt == qt) {
            const int r0 = w * 16 + g, r1 = r0 + 8;
#pragma unroll
            for (int nt = 0; nt < 8; nt++) {
                const int c = nt * 8 + 2 * q;
                if (c     > r0) sc[nt][0] = -1e30f;
                if (c + 1 > r0) sc[nt][1] = -1e30f;
                if (c     > r1) sc[nt][2] = -1e30f;
                if (c + 1 > r1) sc[nt][3] = -1e30f;
            }
        }

        // ---- online softmax (2 rows per thread) ----
        float mx0 = -1e30f, mx1 = -1e30f;
#pragma unroll
        for (int nt = 0; nt < 8; nt++) {
            mx0 = fmaxf(mx0, fmaxf(sc[nt][0], sc[nt][1]));
            mx1 = fmaxf(mx1, fmaxf(sc[nt][2], sc[nt][3]));
        }
        mx0 = fmaxf(mx0, __shfl_xor_sync(0xffffffffu, mx0, 1));
        mx0 = fmaxf(mx0, __shfl_xor_sync(0xffffffffu, mx0, 2));
        mx1 = fmaxf(mx1, __shfl_xor_sync(0xffffffffu, mx1, 1));
        mx1 = fmaxf(mx1, __shfl_xor_sync(0xffffffffu, mx1, 2));

        const float mn0 = fmaxf(mrow[0], mx0);
        const float mn1 = fmaxf(mrow[1], mx1);
        const float al0 = __expf(mrow[0] - mn0);
        const float al1 = __expf(mrow[1] - mn1);
        mrow[0] = mn0; mrow[1] = mn1;

        float s0 = 0.f, s1 = 0.f;
#pragma unroll
        for (int nt = 0; nt < 8; nt++) {
            sc[nt][0] = __expf(sc[nt][0] - mn0); s0 += sc[nt][0];
            sc[nt][1] = __expf(sc[nt][1] - mn0); s0 += sc[nt][1];
            sc[nt][2] = __expf(sc[nt][2] - mn1); s1 += sc[nt][2];
            sc[nt][3] = __expf(sc[nt][3] - mn1); s1 += sc[nt][3];
        }
        s0 += __shfl_xor_sync(0xffffffffu, s0, 1);
        s0 += __shfl_xor_sync(0xffffffffu, s0, 2);
        s1 += __shfl_xor_sync(0xffffffffu, s1, 1);
        s1 += __shfl_xor_sync(0xffffffffu, s1, 2);
        lsum[0] = lsum[0] * al0 + s0;
        lsum[1] = lsum[1] * al1 + s1;

#pragma unroll
        for (int nt = 0; nt < 8; nt++) {
            so[nt][0] *= al0; so[nt][1] *= al0;
            so[nt][2] *= al1; so[nt][3] *= al1;
        }

        // ---- store P (tf32) into its own buffer (own warp rows only) ----
        {
            const int r0 = w * 16 + g;
#pragma unroll
            for (int nt = 0; nt < 8; nt++) {
                const int c = nt * 8 + 2 * q;
                *(float2*)&Ps[r0 * SKA + c] =
                    make_float2(to_tf32(sc[nt][0]), to_tf32(sc[nt][1]));
                *(float2*)&Ps[(r0 + 8) * SKA + c] =
                    make_float2(to_tf32(sc[nt][2]), to_tf32(sc[nt][3]));
            }
        }
        __syncwarp();   // P rows owned/read by this warp only

        // ---- O += P V  (b-frags straight from pre-transposed V) ----
#pragma unroll
        for (int kd = 0; kd < 8; kd++) {
            uint32_t pf[4], bf[4][4];
            ldsm_x4(pf, sP + (uint32_t)(((w * 16) * SKA + kd * 8) * 4) + aoff);
#pragma unroll
            for (int pr = 0; pr < 4; pr++)
                ldsm_x4(bf[pr], sVt + (uint32_t)(((pr * 16) * SKA + kd * 8) * 4) + boff);
#pragma unroll
            for (int nt = 0; nt < 8; nt++)
                mma_tf32(so[nt], pf, bf[nt >> 1] + (nt & 1) * 2);
        }
    }

    // ---- normalize + store y (tf32 for GEMM2 consumption) ----
    {
        const float inv0 = 1.f / lsum[0];
        const float inv1 = 1.f / lsum[1];
        const int r0 = q0 + w * 16 + g;
        float* yb = g_y + (size_t)b * TLEN * CDIM + h * DH;
#pragma unroll
        for (int nt = 0; nt < 8; nt++) {
            const int c = nt * 8 + 2 * q;
            *(float2*)(yb + (size_t)r0 * CDIM + c) =
                make_float2(to_tf32(so[nt][0] * inv0), to_tf32(so[nt][1] * inv0));
            *(float2*)(yb + (size_t)(r0 + 8) * CDIM + c) =
                make_float2(to_tf32(so[nt][2] * inv1), to_tf32(so[nt][3] * inv1));
        }
    }
}

// ---------------------------------------------------------------------------
extern "C" void kernel_launch(void* const* d_in, const int* in_sizes, int n_in,
                              void* d_out, int out_size)
{
    const float* x      = (const float*)d_in[0];
    const float* W_attn = (const float*)d_in[1];
    const float* b_attn = (const float*)d_in[2];
    const float* W_proj = (const float*)d_in[3];
    const float* b_proj = (const float*)d_in[4];
    float* out = (float*)d_out;

    cudaFuncSetAttribute(gemm_ls_kernel, cudaFuncAttributeMaxDynamicSharedMemorySize, GSMEM);
    cudaFuncSetAttribute(attn_vt_kernel, cudaFuncAttributeMaxDynamicSharedMemorySize, ASMEM);

    // 0) pre-convert x; transpose+convert weights
    cvt_kernel<<<(MROWS * CDIM) / (256 * 4), 256>>>(x);
    {
        dim3 tb(32, 8);
        transpose_kernel<<<dim3((3 * CDIM) / 32, CDIM / 32), tb>>>(W_attn, CDIM, 3 * CDIM, 0);
        transpose_kernel<<<dim3(CDIM / 32, CDIM / 32), tb>>>(W_proj, CDIM, CDIM, 1);
    }
    // 1) qkv = x @ W_attn + b_attn (tf32-rounded)
    {
        dim3 grid((3 * CDIM) / 128, MROWS / 128);
        gemm_ls_kernel<<<grid, 128, GSMEM>>>(b_attn, nullptr, MROWS, 3 * CDIM, CDIM, 0);
    }
    // 1b) transpose V slice: g_qkv -> g_vt[b,h,d,t]
    {
        dim3 tb(32, 8);
        vtrans_kernel<<<dim3(TLEN / 32, 2 * HN, BSZ), tb>>>();
    }
    // 2) flash attention -> g_y (tf32-rounded)
    {
        dim3 grid(TLEN / 64, HN, BSZ);
        attn_vt_kernel<<<grid, 128, ASMEM>>>();
    }
    // 3) out = y @ W_proj + b_proj
    {
        dim3 grid(CDIM / 128, MROWS / 128);
        gemm_ls_kernel<<<grid, 128, GSMEM>>>(b_proj, out, MROWS, CDIM, CDIM, 1);
    }
}